// round 1
// baseline (speedup 1.0000x reference)
#include <cuda_runtime.h>
#include <cuda_bf16.h>

// Problem constants (fixed by reference setup)
#define HS 8
#define WS 8
#define NWIN_X 32           // 256/8
#define NWIN_Y 32
#define NTOK 64             // tokens per window
#define DIM 192
#define NH 6
#define HEAD_DIM 32
#define POS_DIM 12
#define NPOS 225            // (2*8-1)^2
#define SCALE 0.17677669529663689f   // 32^-0.5
#define PADW 193            // padded row stride for q/k/v tiles (odd -> conflict free)
#define PADS 65             // padded row stride for score tile

__device__ float g_pos[NPOS * NH];   // RPE MLP output table

// ---------------------------------------------------------------------------
// Kernel A: tiny RPE MLP -> g_pos[225][6]
// ---------------------------------------------------------------------------
__device__ __forceinline__ void ln_relu(float* x, const float* g, const float* b, float* y) {
    float m = 0.f;
#pragma unroll
    for (int j = 0; j < POS_DIM; ++j) m += x[j];
    m *= (1.0f / POS_DIM);
    float v = 0.f;
#pragma unroll
    for (int j = 0; j < POS_DIM; ++j) { float d = x[j] - m; v += d * d; }
    v *= (1.0f / POS_DIM);
    float inv = rsqrtf(v + 1e-5f);
#pragma unroll
    for (int j = 0; j < POS_DIM; ++j) {
        float t = (x[j] - m) * inv * g[j] + b[j];
        y[j] = t > 0.f ? t : 0.f;
    }
}

__global__ void rpe_mlp_kernel(
    const float* __restrict__ w_proj, const float* __restrict__ b_proj,
    const float* __restrict__ ln1_g, const float* __restrict__ ln1_b,
    const float* __restrict__ w1, const float* __restrict__ b1,
    const float* __restrict__ ln2_g, const float* __restrict__ ln2_b,
    const float* __restrict__ w2, const float* __restrict__ b2,
    const float* __restrict__ ln3_g, const float* __restrict__ ln3_b,
    const float* __restrict__ w3, const float* __restrict__ b3)
{
    int m = blockIdx.x * blockDim.x + threadIdx.x;
    if (m >= NPOS) return;
    float in0 = (float)(m / (2 * WS - 1) - (HS - 1));  // dy
    float in1 = (float)(m % (2 * WS - 1) - (WS - 1));  // dx

    float x[POS_DIM], y[POS_DIM];
#pragma unroll
    for (int j = 0; j < POS_DIM; ++j)
        x[j] = in0 * w_proj[j] + in1 * w_proj[POS_DIM + j] + b_proj[j];

    ln_relu(x, ln1_g, ln1_b, y);
#pragma unroll
    for (int j = 0; j < POS_DIM; ++j) {
        float s = b1[j];
#pragma unroll
        for (int kk = 0; kk < POS_DIM; ++kk) s += y[kk] * w1[kk * POS_DIM + j];
        x[j] = s;
    }
    ln_relu(x, ln2_g, ln2_b, y);
#pragma unroll
    for (int j = 0; j < POS_DIM; ++j) {
        float s = b2[j];
#pragma unroll
        for (int kk = 0; kk < POS_DIM; ++kk) s += y[kk] * w2[kk * POS_DIM + j];
        x[j] = s;
    }
    ln_relu(x, ln3_g, ln3_b, y);
#pragma unroll
    for (int h = 0; h < NH; ++h) {
        float s = b3[h];
#pragma unroll
        for (int kk = 0; kk < POS_DIM; ++kk) s += y[kk] * w3[kk * NH + h];
        g_pos[m * NH + h] = s;
    }
}

// ---------------------------------------------------------------------------
// Kernel B: one CTA per 8x8 window, all 6 heads.
// smem: q,k,v tiles 64x193 fp32 each + score tile 64x65 + pos table.
// ---------------------------------------------------------------------------
#define SMEM_FLOATS (3 * NTOK * PADW + NTOK * PADS + NPOS * NH + 2)
#define SMEM_BYTES (SMEM_FLOATS * 4)

__global__ __launch_bounds__(256, 1) void attn_kernel(
    const float* __restrict__ q, const float* __restrict__ k,
    const float* __restrict__ v, float* __restrict__ out)
{
    extern __shared__ float sm[];
    float* sQ = sm;                       // 64*193
    float* sK = sQ + NTOK * PADW;
    float* sV = sK + NTOK * PADW;
    float* sS = sV + NTOK * PADW;         // 64*65
    float* sPos = sS + NTOK * PADS;       // 225*6

    const int w = blockIdx.x;
    const int b = w >> 10;                // / (32*32)
    const int wy = (w >> 5) & 31;
    const int wx = w & 31;
    const int tid = threadIdx.x;

    // pos table -> smem
    for (int i = tid; i < NPOS * NH; i += 256) sPos[i] = g_pos[i];

    // stage window: token n at (y,x) = (wy*8 + n/8, wx*8 + n%8)
    // window-row = 8 tokens * 192 ch = 1536 contiguous floats -> coalesced
    for (int i = tid; i < NTOK * DIM; i += 256) {
        int n = i / DIM;
        int c = i - n * DIM;
        int y = wy * HS + (n >> 3);
        int x = wx * WS + (n & 7);
        int g = ((b * 256 + y) * 256 + x) * DIM + c;
        sQ[n * PADW + c] = q[g] * SCALE;
        sK[n * PADW + c] = k[g];
        sV[n * PADW + c] = v[g];
    }
    __syncthreads();

    const int ty = tid >> 4;     // 0..15  (row group)
    const int tx = tid & 15;     // 0..15  (col group)

#pragma unroll 1
    for (int h = 0; h < NH; ++h) {
        const int co = h * HEAD_DIM;

        // ---- S = (Q*scale) K^T : 4x4 register tile per thread ----
        float acc[4][4] = {};
#pragma unroll 8
        for (int d = 0; d < HEAD_DIM; ++d) {
            float qf[4], kf[4];
#pragma unroll
            for (int a = 0; a < 4; ++a) qf[a] = sQ[(16 * a + ty) * PADW + co + d];
#pragma unroll
            for (int bb = 0; bb < 4; ++bb) kf[bb] = sK[(16 * bb + tx) * PADW + co + d];
#pragma unroll
            for (int a = 0; a < 4; ++a)
#pragma unroll
                for (int bb = 0; bb < 4; ++bb) acc[a][bb] = fmaf(qf[a], kf[bb], acc[a][bb]);
        }

        // ---- bias + softmax, fully register resident (rows spread over 16 lanes) ----
#pragma unroll
        for (int a = 0; a < 4; ++a) {
            const int i = 16 * a + ty;
            const int yi = i >> 3, xi = i & 7;
            float mx = -1e30f;
#pragma unroll
            for (int bb = 0; bb < 4; ++bb) {
                const int j = 16 * bb + tx;
                const int yj = j >> 3, xj = j & 7;
                const int idx = (yi - yj + HS - 1) * (2 * WS - 1) + (xi - xj + WS - 1);
                acc[a][bb] += sPos[idx * NH + h];
                mx = fmaxf(mx, acc[a][bb]);
            }
#pragma unroll
            for (int off = 8; off >= 1; off >>= 1)
                mx = fmaxf(mx, __shfl_xor_sync(0xffffffffu, mx, off));
            float s = 0.f;
#pragma unroll
            for (int bb = 0; bb < 4; ++bb) {
                acc[a][bb] = __expf(acc[a][bb] - mx);
                s += acc[a][bb];
            }
#pragma unroll
            for (int off = 8; off >= 1; off >>= 1)
                s += __shfl_xor_sync(0xffffffffu, s, off);
            const float inv = __frcp_rn(s);
#pragma unroll
            for (int bb = 0; bb < 4; ++bb) acc[a][bb] *= inv;
        }

        // ---- stage P (wait for previous head's PV reads first) ----
        __syncthreads();
#pragma unroll
        for (int a = 0; a < 4; ++a)
#pragma unroll
            for (int bb = 0; bb < 4; ++bb)
                sS[(16 * a + ty) * PADS + 16 * bb + tx] = acc[a][bb];
        __syncthreads();

        // ---- O = P V : 4x2 register tile per thread ----
        float o[4][2] = {};
#pragma unroll 8
        for (int m = 0; m < NTOK; ++m) {
            float pf[4];
#pragma unroll
            for (int a = 0; a < 4; ++a) pf[a] = sS[(16 * a + ty) * PADS + m];
            const float vf0 = sV[m * PADW + co + tx];
            const float vf1 = sV[m * PADW + co + tx + 16];
#pragma unroll
            for (int a = 0; a < 4; ++a) {
                o[a][0] = fmaf(pf[a], vf0, o[a][0]);
                o[a][1] = fmaf(pf[a], vf1, o[a][1]);
            }
        }

        // ---- write out: out[b][y][x][c] (same layout as input) ----
#pragma unroll
        for (int a = 0; a < 4; ++a) {
            const int i = 16 * a + ty;
            const int y = wy * HS + (i >> 3);
            const int x = wx * WS + (i & 7);
            const int g = ((b * 256 + y) * 256 + x) * DIM + co + tx;
            out[g] = o[a][0];
            out[g + 16] = o[a][1];
        }
    }
}

// ---------------------------------------------------------------------------
extern "C" void kernel_launch(void* const* d_in, const int* in_sizes, int n_in,
                              void* d_out, int out_size)
{
    const float* q = (const float*)d_in[0];
    const float* k = (const float*)d_in[1];
    const float* v = (const float*)d_in[2];
    // d_in[3] = H, d_in[4] = W (int32, fixed 256 by the problem instance)
    const float* w_proj = (const float*)d_in[5];
    const float* b_proj = (const float*)d_in[6];
    const float* ln1_g  = (const float*)d_in[7];
    const float* ln1_b  = (const float*)d_in[8];
    const float* w1     = (const float*)d_in[9];
    const float* b1     = (const float*)d_in[10];
    const float* ln2_g  = (const float*)d_in[11];
    const float* ln2_b  = (const float*)d_in[12];
    const float* w2     = (const float*)d_in[13];
    const float* b2     = (const float*)d_in[14];
    const float* ln3_g  = (const float*)d_in[15];
    const float* ln3_b  = (const float*)d_in[16];
    const float* w3     = (const float*)d_in[17];
    const float* b3     = (const float*)d_in[18];

    int B = in_sizes[0] / (256 * 256 * DIM);

    cudaFuncSetAttribute(attn_kernel, cudaFuncAttributeMaxDynamicSharedMemorySize, SMEM_BYTES);

    rpe_mlp_kernel<<<1, 256>>>(w_proj, b_proj, ln1_g, ln1_b, w1, b1,
                               ln2_g, ln2_b, w2, b2, ln3_g, ln3_b, w3, b3);
    attn_kernel<<<B * NWIN_Y * NWIN_X, 256, SMEM_BYTES>>>(q, k, v, (float*)d_out);
}

// round 3
// speedup vs baseline: 2.1038x; 2.1038x over previous
#include <cuda_runtime.h>
#include <cuda_bf16.h>
#include <cstdint>

// Problem constants (fixed by reference setup)
#define HSZ 8
#define WSZ 8
#define NTOK 64             // tokens per window
#define DIM 192
#define NH 6
#define HEAD_DIM 32
#define POS_DIM 12
#define NPOS 225            // (2*8-1)^2
#define SCALE 0.17677669529663689f   // 32^-0.5

#define PADQ 33             // row stride for per-head q/k/v tiles
#define PADP 66             // row stride for P tile (even -> float2 aligned, 2-way max conflict)

// smem layout (floats)
#define SM_Q   0
#define SM_K   (NTOK * PADQ)
#define SM_V   (2 * NTOK * PADQ)
#define SM_P   (3 * NTOK * PADQ)
#define SM_POS (SM_P + NTOK * PADP)
#define SM_RED (SM_POS + NPOS * NH)
#define SM_TOT (SM_RED + 256)
#define SMEM_BYTES (SM_TOT * 4)

__device__ float g_pos[NPOS * NH];   // RPE MLP output table

// ---------------------------------------------------------------------------
// Kernel A: tiny RPE MLP -> g_pos[225][6]
// ---------------------------------------------------------------------------
__device__ __forceinline__ void ln_relu(float* x, const float* g, const float* b, float* y) {
    float m = 0.f;
#pragma unroll
    for (int j = 0; j < POS_DIM; ++j) m += x[j];
    m *= (1.0f / POS_DIM);
    float v = 0.f;
#pragma unroll
    for (int j = 0; j < POS_DIM; ++j) { float d = x[j] - m; v += d * d; }
    v *= (1.0f / POS_DIM);
    float inv = rsqrtf(v + 1e-5f);
#pragma unroll
    for (int j = 0; j < POS_DIM; ++j) {
        float t = (x[j] - m) * inv * g[j] + b[j];
        y[j] = t > 0.f ? t : 0.f;
    }
}

__global__ void rpe_mlp_kernel(
    const float* __restrict__ w_proj, const float* __restrict__ b_proj,
    const float* __restrict__ ln1_g, const float* __restrict__ ln1_b,
    const float* __restrict__ w1, const float* __restrict__ b1,
    const float* __restrict__ ln2_g, const float* __restrict__ ln2_b,
    const float* __restrict__ w2, const float* __restrict__ b2,
    const float* __restrict__ ln3_g, const float* __restrict__ ln3_b,
    const float* __restrict__ w3, const float* __restrict__ b3)
{
    int m = blockIdx.x * blockDim.x + threadIdx.x;
    if (m >= NPOS) return;
    float in0 = (float)(m / (2 * WSZ - 1) - (HSZ - 1));  // dy
    float in1 = (float)(m % (2 * WSZ - 1) - (WSZ - 1));  // dx

    float x[POS_DIM], y[POS_DIM];
#pragma unroll
    for (int j = 0; j < POS_DIM; ++j)
        x[j] = in0 * w_proj[j] + in1 * w_proj[POS_DIM + j] + b_proj[j];

    ln_relu(x, ln1_g, ln1_b, y);
#pragma unroll
    for (int j = 0; j < POS_DIM; ++j) {
        float s = b1[j];
#pragma unroll
        for (int kk = 0; kk < POS_DIM; ++kk) s += y[kk] * w1[kk * POS_DIM + j];
        x[j] = s;
    }
    ln_relu(x, ln2_g, ln2_b, y);
#pragma unroll
    for (int j = 0; j < POS_DIM; ++j) {
        float s = b2[j];
#pragma unroll
        for (int kk = 0; kk < POS_DIM; ++kk) s += y[kk] * w2[kk * POS_DIM + j];
        x[j] = s;
    }
    ln_relu(x, ln3_g, ln3_b, y);
#pragma unroll
    for (int h = 0; h < NH; ++h) {
        float s = b3[h];
#pragma unroll
        for (int kk = 0; kk < POS_DIM; ++kk) s += y[kk] * w3[kk * NH + h];
        g_pos[m * NH + h] = s;
    }
}

// ---------------------------------------------------------------------------
// tf32 helpers
// ---------------------------------------------------------------------------
__device__ __forceinline__ uint32_t f2tf32(float x) {
    uint32_t r;
    asm("cvt.rna.tf32.f32 %0, %1;" : "=r"(r) : "f"(x));
    return r;
}

__device__ __forceinline__ void mma_tf32(float c[4],
    uint32_t a0, uint32_t a1, uint32_t a2, uint32_t a3,
    uint32_t b0, uint32_t b1)
{
    asm volatile(
        "mma.sync.aligned.m16n8k8.row.col.f32.tf32.tf32.f32 "
        "{%0,%1,%2,%3}, {%4,%5,%6,%7}, {%8,%9}, {%0,%1,%2,%3};"
        : "+f"(c[0]), "+f"(c[1]), "+f"(c[2]), "+f"(c[3])
        : "r"(a0), "r"(a1), "r"(a2), "r"(a3), "r"(b0), "r"(b1));
}

// ---------------------------------------------------------------------------
// Kernel B: one CTA per 8x8 window; 8 warps = (4 m-tiles) x (2 n-halves).
// Per-head staging of q/k/v slices (64x32) -> tf32 MMA for QK^T and PV.
// ---------------------------------------------------------------------------
__global__ __launch_bounds__(256, 3) void attn_kernel(
    const float* __restrict__ q, const float* __restrict__ k,
    const float* __restrict__ v, float* __restrict__ out)
{
    extern __shared__ float sm[];
    uint32_t* smu = (uint32_t*)sm;

    const int tid = threadIdx.x;
    const int lane = tid & 31;
    const int wid = tid >> 5;
    const int gid = lane >> 2;     // 0..7
    const int tig = lane & 3;      // 0..3
    const int mi = wid & 3;        // m-tile (16 rows)
    const int nj = wid >> 2;       // n-half (32 cols)

    const int w = blockIdx.x;
    const int b = w >> 10;
    const int wy = (w >> 5) & 31;
    const int wx = w & 31;

    // pos table -> smem (first use is after head-0 stage barrier)
    for (int i = tid; i < NPOS * NH; i += 256) sm[SM_POS + i] = g_pos[i];

    // stage addressing: thread loads token t = tid>>5 (one token per warp, 32 ch)
    const int st = tid >> 5;             // token for stage (first of 8)
    const int sd = tid & 31;             // channel

    const int r0 = mi * 16 + gid;        // rows owned by this lane (c0,c1)
    const int r1 = r0 + 8;               // rows owned (c2,c3)
    const int y0 = r0 >> 3, x0 = r0 & 7;
    const int y1 = r1 >> 3, x1 = r1 & 7;

#pragma unroll 1
    for (int h = 0; h < NH; ++h) {
        // ---- stage per-head slices (tf32-rounded), coalesced 128B/token ----
#pragma unroll
        for (int it = 0; it < 8; ++it) {
            int t = st + it * 8;
            int y = wy * HSZ + (t >> 3);
            int x = wx * WSZ + (t & 7);
            int g = ((b * 256 + y) * 256 + x) * DIM + h * HEAD_DIM + sd;
            int so = t * PADQ + sd;
            smu[SM_Q + so] = f2tf32(q[g] * SCALE);
            smu[SM_K + so] = f2tf32(k[g]);
            smu[SM_V + so] = f2tf32(v[g]);
        }
        __syncthreads();

        // ---- S tile = Q K^T : warp computes rows [mi*16,+16), cols [nj*32,+32) ----
        float sc[4][4];
#pragma unroll
        for (int nt = 0; nt < 4; ++nt)
#pragma unroll
            for (int c = 0; c < 4; ++c) sc[nt][c] = 0.f;

#pragma unroll
        for (int kt = 0; kt < 4; ++kt) {
            const int d0 = kt * 8 + tig;
            uint32_t a0 = smu[SM_Q + r0 * PADQ + d0];
            uint32_t a1 = smu[SM_Q + r1 * PADQ + d0];
            uint32_t a2 = smu[SM_Q + r0 * PADQ + d0 + 4];
            uint32_t a3 = smu[SM_Q + r1 * PADQ + d0 + 4];
#pragma unroll
            for (int nt = 0; nt < 4; ++nt) {
                const int tok = nj * 32 + nt * 8 + gid;
                uint32_t b0 = smu[SM_K + tok * PADQ + d0];
                uint32_t b1 = smu[SM_K + tok * PADQ + d0 + 4];
                mma_tf32(sc[nt], a0, a1, a2, a3, b0, b1);
            }
        }

        // ---- bias add + row max (local 8 cols, then across tig lanes) ----
        float mx0 = -1e30f, mx1 = -1e30f;
#pragma unroll
        for (int nt = 0; nt < 4; ++nt) {
#pragma unroll
            for (int cc = 0; cc < 2; ++cc) {
                const int j = nj * 32 + nt * 8 + 2 * tig + cc;
                const int yj = j >> 3, xj = j & 7;
                sc[nt][cc]     += sm[SM_POS + ((y0 - yj + 7) * 15 + (x0 - xj + 7)) * NH + h];
                sc[nt][2 + cc] += sm[SM_POS + ((y1 - yj + 7) * 15 + (x1 - xj + 7)) * NH + h];
                mx0 = fmaxf(mx0, sc[nt][cc]);
                mx1 = fmaxf(mx1, sc[nt][2 + cc]);
            }
        }
        mx0 = fmaxf(mx0, __shfl_xor_sync(0xffffffffu, mx0, 1));
        mx0 = fmaxf(mx0, __shfl_xor_sync(0xffffffffu, mx0, 2));
        mx1 = fmaxf(mx1, __shfl_xor_sync(0xffffffffu, mx1, 1));
        mx1 = fmaxf(mx1, __shfl_xor_sync(0xffffffffu, mx1, 2));
        if (tig == 0) {
            sm[SM_RED + nj * 64 + r0] = mx0;
            sm[SM_RED + nj * 64 + r1] = mx1;
        }
        __syncthreads();
        mx0 = fmaxf(sm[SM_RED + r0], sm[SM_RED + 64 + r0]);
        mx1 = fmaxf(sm[SM_RED + r1], sm[SM_RED + 64 + r1]);

        // ---- exp + row sum ----
        float s0 = 0.f, s1 = 0.f;
#pragma unroll
        for (int nt = 0; nt < 4; ++nt) {
#pragma unroll
            for (int cc = 0; cc < 2; ++cc) {
                sc[nt][cc]     = __expf(sc[nt][cc] - mx0);
                sc[nt][2 + cc] = __expf(sc[nt][2 + cc] - mx1);
                s0 += sc[nt][cc];
                s1 += sc[nt][2 + cc];
            }
        }
        s0 += __shfl_xor_sync(0xffffffffu, s0, 1);
        s0 += __shfl_xor_sync(0xffffffffu, s0, 2);
        s1 += __shfl_xor_sync(0xffffffffu, s1, 1);
        s1 += __shfl_xor_sync(0xffffffffu, s1, 2);
        if (tig == 0) {
            sm[SM_RED + 128 + nj * 64 + r0] = s0;
            sm[SM_RED + 128 + nj * 64 + r1] = s1;
        }
        __syncthreads();
        const float inv0 = __frcp_rn(sm[SM_RED + 128 + r0] + sm[SM_RED + 192 + r0]);
        const float inv1 = __frcp_rn(sm[SM_RED + 128 + r1] + sm[SM_RED + 192 + r1]);

        // ---- normalize + store P (float2, aligned: PADP even) ----
#pragma unroll
        for (int nt = 0; nt < 4; ++nt) {
            const int col = nj * 32 + nt * 8 + 2 * tig;
            float2 p01 = make_float2(sc[nt][0] * inv0, sc[nt][1] * inv0);
            float2 p23 = make_float2(sc[nt][2] * inv1, sc[nt][3] * inv1);
            *(float2*)&sm[SM_P + r0 * PADP + col] = p01;
            *(float2*)&sm[SM_P + r1 * PADP + col] = p23;
        }
        __syncthreads();

        // ---- O tile = P V : warp computes rows [mi*16,+16), cols [nj*16,+16) ----
        float oc[2][4];
#pragma unroll
        for (int nt = 0; nt < 2; ++nt)
#pragma unroll
            for (int c = 0; c < 4; ++c) oc[nt][c] = 0.f;

#pragma unroll
        for (int kt = 0; kt < 8; ++kt) {
            const int t0 = kt * 8 + tig;
            uint32_t a0 = smu[SM_P + r0 * PADP + t0];
            uint32_t a1 = smu[SM_P + r1 * PADP + t0];
            uint32_t a2 = smu[SM_P + r0 * PADP + t0 + 4];
            uint32_t a3 = smu[SM_P + r1 * PADP + t0 + 4];
#pragma unroll
            for (int nt = 0; nt < 2; ++nt) {
                const int dim = nj * 16 + nt * 8 + gid;
                uint32_t b0 = smu[SM_V + t0 * PADQ + dim];
                uint32_t b1 = smu[SM_V + (t0 + 4) * PADQ + dim];
                mma_tf32(oc[nt], a0, a1, a2, a3, b0, b1);
            }
        }

        // ---- write O (float2 pairs; same layout as input) ----
        {
            const int gy0 = wy * HSZ + y0, gx0 = wx * WSZ + x0;
            const int gy1 = wy * HSZ + y1, gx1 = wx * WSZ + x1;
            const int base0 = ((b * 256 + gy0) * 256 + gx0) * DIM + h * HEAD_DIM;
            const int base1 = ((b * 256 + gy1) * 256 + gx1) * DIM + h * HEAD_DIM;
#pragma unroll
            for (int nt = 0; nt < 2; ++nt) {
                const int col = nj * 16 + nt * 8 + 2 * tig;
                *(float2*)&out[base0 + col] = make_float2(oc[nt][0], oc[nt][1]);
                *(float2*)&out[base1 + col] = make_float2(oc[nt][2], oc[nt][3]);
            }
        }
        __syncthreads();   // protect sQ/sK/sV/sP before next head's stage
    }
}

// ---------------------------------------------------------------------------
extern "C" void kernel_launch(void* const* d_in, const int* in_sizes, int n_in,
                              void* d_out, int out_size)
{
    const float* q = (const float*)d_in[0];
    const float* k = (const float*)d_in[1];
    const float* v = (const float*)d_in[2];
    // d_in[3] = H, d_in[4] = W (int32, fixed 256)
    const float* w_proj = (const float*)d_in[5];
    const float* b_proj = (const float*)d_in[6];
    const float* ln1_g  = (const float*)d_in[7];
    const float* ln1_b  = (const float*)d_in[8];
    const float* w1     = (const float*)d_in[9];
    const float* b1     = (const float*)d_in[10];
    const float* ln2_g  = (const float*)d_in[11];
    const float* ln2_b  = (const float*)d_in[12];
    const float* w2     = (const float*)d_in[13];
    const float* b2     = (const float*)d_in[14];
    const float* ln3_g  = (const float*)d_in[15];
    const float* ln3_b  = (const float*)d_in[16];
    const float* w3     = (const float*)d_in[17];
    const float* b3     = (const float*)d_in[18];

    int B = in_sizes[0] / (256 * 256 * DIM);

    cudaFuncSetAttribute(attn_kernel, cudaFuncAttributeMaxDynamicSharedMemorySize, SMEM_BYTES);

    rpe_mlp_kernel<<<1, 256>>>(w_proj, b_proj, ln1_g, ln1_b, w1, b1,
                               ln2_g, ln2_b, w2, b2, ln3_g, ln3_b, w3, b3);
    attn_kernel<<<B * 1024, 256, SMEM_BYTES>>>(q, k, v, (float*)d_out);
}

// round 7
// speedup vs baseline: 5.2984x; 2.5185x over previous
#include <cuda_runtime.h>
#include <cuda_fp16.h>
#include <cstdint>

// Problem constants (fixed by reference setup)
#define HSZ 8
#define WSZ 8
#define NTOK 64
#define DIM 192
#define NH 6
#define HEAD_DIM 32
#define POS_DIM 12
#define NPOS 225
#define SCALE 0.17677669529663689f   // 32^-0.5

#define PADH 40      // halves per row, Q/K/V tiles (80B rows -> LDSM conflict-free)
#define PADB 72      // halves per row, bias tile (144B rows -> 16B aligned, conflict-free)

// smem (in halves): two head slots, each {Q,K,V: 64*PADH, B: 64*PADB}
#define SLOT_H   (3 * 64 * PADH + 64 * PADB)
#define SMH_Q(s) ((s) * SLOT_H)
#define SMH_K(s) (SMH_Q(s) + 64 * PADH)
#define SMH_V(s) (SMH_K(s) + 64 * PADH)
#define SMH_B(s) (SMH_V(s) + 64 * PADH)
#define SMH_TOT  (2 * SLOT_H)
#define SMEM_BYTES (SMH_TOT * 2)

__device__ float g_pos[NPOS * NH];                  // RPE MLP output
__device__ __align__(16) __half g_rpb[NH * 64 * 64]; // expanded bias table

// ---------------------------------------------------------------------------
// Kernel A: tiny RPE MLP -> g_pos[225][6]
// ---------------------------------------------------------------------------
__device__ __forceinline__ void ln_relu(float* x, const float* g, const float* b, float* y) {
    float m = 0.f;
#pragma unroll
    for (int j = 0; j < POS_DIM; ++j) m += x[j];
    m *= (1.0f / POS_DIM);
    float v = 0.f;
#pragma unroll
    for (int j = 0; j < POS_DIM; ++j) { float d = x[j] - m; v += d * d; }
    v *= (1.0f / POS_DIM);
    float inv = rsqrtf(v + 1e-5f);
#pragma unroll
    for (int j = 0; j < POS_DIM; ++j) {
        float t = (x[j] - m) * inv * g[j] + b[j];
        y[j] = t > 0.f ? t : 0.f;
    }
}

__global__ void rpe_mlp_kernel(
    const float* __restrict__ w_proj, const float* __restrict__ b_proj,
    const float* __restrict__ ln1_g, const float* __restrict__ ln1_b,
    const float* __restrict__ w1, const float* __restrict__ b1,
    const float* __restrict__ ln2_g, const float* __restrict__ ln2_b,
    const float* __restrict__ w2, const float* __restrict__ b2,
    const float* __restrict__ ln3_g, const float* __restrict__ ln3_b,
    const float* __restrict__ w3, const float* __restrict__ b3)
{
    int m = blockIdx.x * blockDim.x + threadIdx.x;
    if (m >= NPOS) return;
    float in0 = (float)(m / (2 * WSZ - 1) - (HSZ - 1));
    float in1 = (float)(m % (2 * WSZ - 1) - (WSZ - 1));

    float x[POS_DIM], y[POS_DIM];
#pragma unroll
    for (int j = 0; j < POS_DIM; ++j)
        x[j] = in0 * w_proj[j] + in1 * w_proj[POS_DIM + j] + b_proj[j];

    ln_relu(x, ln1_g, ln1_b, y);
#pragma unroll
    for (int j = 0; j < POS_DIM; ++j) {
        float s = b1[j];
#pragma unroll
        for (int kk = 0; kk < POS_DIM; ++kk) s += y[kk] * w1[kk * POS_DIM + j];
        x[j] = s;
    }
    ln_relu(x, ln2_g, ln2_b, y);
#pragma unroll
    for (int j = 0; j < POS_DIM; ++j) {
        float s = b2[j];
#pragma unroll
        for (int kk = 0; kk < POS_DIM; ++kk) s += y[kk] * w2[kk * POS_DIM + j];
        x[j] = s;
    }
    ln_relu(x, ln3_g, ln3_b, y);
#pragma unroll
    for (int h = 0; h < NH; ++h) {
        float s = b3[h];
#pragma unroll
        for (int kk = 0; kk < POS_DIM; ++kk) s += y[kk] * w3[kk * NH + h];
        g_pos[m * NH + h] = s;
    }
}

// Expand to g_rpb[h][i][j] (fp16)
__global__ void rpe_expand_kernel() {
    int i = blockIdx.x * 256 + threadIdx.x;   // 0 .. 6*4096-1
    int h = i >> 12;
    int r = (i >> 6) & 63;
    int c = i & 63;
    int dy = (r >> 3) - (c >> 3) + 7;
    int dx = (r & 7) - (c & 7) + 7;
    g_rpb[i] = __float2half(g_pos[(dy * 15 + dx) * NH + h]);
}

// ---------------------------------------------------------------------------
// MMA / LDSM helpers
// ---------------------------------------------------------------------------
__device__ __forceinline__ uint32_t sh_addr(const void* p) {
    return (uint32_t)__cvta_generic_to_shared(p);
}
__device__ __forceinline__ void ldsm_x4(uint32_t& r0, uint32_t& r1, uint32_t& r2, uint32_t& r3, uint32_t a) {
    asm volatile("ldmatrix.sync.aligned.m8n8.x4.shared.b16 {%0,%1,%2,%3},[%4];"
                 : "=r"(r0), "=r"(r1), "=r"(r2), "=r"(r3) : "r"(a));
}
__device__ __forceinline__ void ldsm_x4_t(uint32_t& r0, uint32_t& r1, uint32_t& r2, uint32_t& r3, uint32_t a) {
    asm volatile("ldmatrix.sync.aligned.m8n8.x4.trans.shared.b16 {%0,%1,%2,%3},[%4];"
                 : "=r"(r0), "=r"(r1), "=r"(r2), "=r"(r3) : "r"(a));
}
__device__ __forceinline__ void mma_f16(float c[4], const uint32_t a[4], uint32_t b0, uint32_t b1) {
    asm volatile("mma.sync.aligned.m16n8k16.row.col.f32.f16.f16.f32 "
                 "{%0,%1,%2,%3},{%4,%5,%6,%7},{%8,%9},{%0,%1,%2,%3};"
                 : "+f"(c[0]), "+f"(c[1]), "+f"(c[2]), "+f"(c[3])
                 : "r"(a[0]), "r"(a[1]), "r"(a[2]), "r"(a[3]), "r"(b0), "r"(b1));
}
__device__ __forceinline__ void st_half8(__half* p, float4 f0, float4 f1) {
    union { __half2 h[4]; uint4 u; } t;
    t.h[0] = __floats2half2_rn(f0.x, f0.y);
    t.h[1] = __floats2half2_rn(f0.z, f0.w);
    t.h[2] = __floats2half2_rn(f1.x, f1.y);
    t.h[3] = __floats2half2_rn(f1.z, f1.w);
    *(uint4*)p = t.u;
}

// ---------------------------------------------------------------------------
// Kernel B: one CTA per 8x8 window. 3 iterations of 2 heads.
// 8 warps = 4 m-tiles x 2 heads; warp computes full 16x64 score rows.
// ---------------------------------------------------------------------------
__global__ __launch_bounds__(256, 3) void attn_kernel(
    const float* __restrict__ q, const float* __restrict__ k,
    const float* __restrict__ v, float* __restrict__ out)
{
    extern __shared__ __half smh[];

    const int tid = threadIdx.x;
    const int lane = tid & 31;
    const int wid = tid >> 5;
    const int g = lane >> 2;       // 0..7
    const int t = lane & 3;        // 0..3
    const int m = wid & 3;         // m-tile
    const int hs = wid >> 2;       // head slot (0/1)

    const int w = blockIdx.x;
    const int b = w >> 10;
    const int wy = (w >> 5) & 31;
    const int wx = w & 31;

    // staging addresses: thread handles token tid>>2, channels (tid&3)*8..+8
    const int stok = tid >> 2;
    const int sch = (tid & 3) * 8;
    const int sy = wy * HSZ + (stok >> 3);
    const int sx = wx * WSZ + (stok & 7);
    const int gtok = ((b * 256 + sy) * 256 + sx) * DIM + sch;
    const int soff = stok * PADH + sch;

    // bias staging: thread handles row tid>>2, 16 halves at col (tid&3)*16
    const int brow = tid >> 2;
    const int bcol = (tid & 3) * 16;

    // this warp's output rows
    const int r0 = m * 16 + g;
    const int r1 = r0 + 8;
    const int obase0 = ((b * 256 + wy * HSZ + (r0 >> 3)) * 256 + wx * WSZ + (r0 & 7)) * DIM;
    const int obase1 = ((b * 256 + wy * HSZ + (r1 >> 3)) * 256 + wx * WSZ + (r1 & 7)) * DIM;

    // LDSM addresses (fixed per warp across iterations except slot base)
    // A (Q): lane -> row m*16 + (lane&7) + ((lane>>3)&1)*8, col base (lane>>4)*8
    const int a_row = m * 16 + (lane & 7) + ((lane >> 3) & 1) * 8;
    const int a_colp = (lane >> 4) * 8;
    // B (K): lane -> row (lane&7) within n8 tile, col (lane>>3)*8
    const int bk_row = lane & 7;
    const int bk_col = (lane >> 3) * 8;
    // B (V, trans): lane -> tok (lane>>3)*8 + (lane&7)
    const int bv_tok = (lane >> 3) * 8 + (lane & 7);

#pragma unroll 1
    for (int it = 0; it < 3; ++it) {
        const int h0 = it * 2;

        // ---- stage 2 heads: Q(scaled),K,V as fp16 + bias tiles ----
#pragma unroll
        for (int s = 0; s < 2; ++s) {
            const int go = gtok + (h0 + s) * HEAD_DIM;
            float4 f0, f1;
            f0 = *(const float4*)(q + go);
            f1 = *(const float4*)(q + go + 4);
            f0.x *= SCALE; f0.y *= SCALE; f0.z *= SCALE; f0.w *= SCALE;
            f1.x *= SCALE; f1.y *= SCALE; f1.z *= SCALE; f1.w *= SCALE;
            st_half8(&smh[SMH_Q(s) + soff], f0, f1);
            f0 = *(const float4*)(k + go);
            f1 = *(const float4*)(k + go + 4);
            st_half8(&smh[SMH_K(s) + soff], f0, f1);
            f0 = *(const float4*)(v + go);
            f1 = *(const float4*)(v + go + 4);
            st_half8(&smh[SMH_V(s) + soff], f0, f1);

            const uint4* src = (const uint4*)&g_rpb[(h0 + s) * 4096 + brow * 64 + bcol];
            uint4 b0 = src[0], b1 = src[1];
            *(uint4*)&smh[SMH_B(s) + brow * PADB + bcol] = b0;
            *(uint4*)&smh[SMH_B(s) + brow * PADB + bcol + 8] = b1;
        }
        __syncthreads();

        const __half* sQ = &smh[SMH_Q(hs)];
        const __half* sK = &smh[SMH_K(hs)];
        const __half* sV = &smh[SMH_V(hs)];
        const __half* sB = &smh[SMH_B(hs)];
        const int head = h0 + hs;

        // ---- S = Q K^T : 16x64 per warp ----
        float sc[8][4];
#pragma unroll
        for (int nt = 0; nt < 8; ++nt)
#pragma unroll
            for (int c = 0; c < 4; ++c) sc[nt][c] = 0.f;

        uint32_t aq[2][4];
#pragma unroll
        for (int kt = 0; kt < 2; ++kt)
            ldsm_x4(aq[kt][0], aq[kt][1], aq[kt][2], aq[kt][3],
                    sh_addr(&sQ[a_row * PADH + kt * 16 + a_colp]));

#pragma unroll
        for (int nt = 0; nt < 8; ++nt) {
            uint32_t b0, b1, b2, b3;
            ldsm_x4(b0, b1, b2, b3, sh_addr(&sK[(nt * 8 + bk_row) * PADH + bk_col]));
            mma_f16(sc[nt], aq[0], b0, b1);
            mma_f16(sc[nt], aq[1], b2, b3);
        }

        // ---- bias add + warp-local softmax (rows r0, r1) ----
        float mx0 = -1e30f, mx1 = -1e30f;
#pragma unroll
        for (int nt = 0; nt < 8; ++nt) {
            float2 f0 = __half22float2(*(const __half2*)&sB[r0 * PADB + nt * 8 + 2 * t]);
            float2 f1 = __half22float2(*(const __half2*)&sB[r1 * PADB + nt * 8 + 2 * t]);
            sc[nt][0] += f0.x; sc[nt][1] += f0.y;
            sc[nt][2] += f1.x; sc[nt][3] += f1.y;
            mx0 = fmaxf(mx0, fmaxf(sc[nt][0], sc[nt][1]));
            mx1 = fmaxf(mx1, fmaxf(sc[nt][2], sc[nt][3]));
        }
        mx0 = fmaxf(mx0, __shfl_xor_sync(0xffffffffu, mx0, 1));
        mx0 = fmaxf(mx0, __shfl_xor_sync(0xffffffffu, mx0, 2));
        mx1 = fmaxf(mx1, __shfl_xor_sync(0xffffffffu, mx1, 1));
        mx1 = fmaxf(mx1, __shfl_xor_sync(0xffffffffu, mx1, 2));

        float s0 = 0.f, s1 = 0.f;
#pragma unroll
        for (int nt = 0; nt < 8; ++nt) {
            sc[nt][0] = __expf(sc[nt][0] - mx0);
            sc[nt][1] = __expf(sc[nt][1] - mx0);
            sc[nt][2] = __expf(sc[nt][2] - mx1);
            sc[nt][3] = __expf(sc[nt][3] - mx1);
            s0 += sc[nt][0] + sc[nt][1];
            s1 += sc[nt][2] + sc[nt][3];
        }
        s0 += __shfl_xor_sync(0xffffffffu, s0, 1);
        s0 += __shfl_xor_sync(0xffffffffu, s0, 2);
        s1 += __shfl_xor_sync(0xffffffffu, s1, 1);
        s1 += __shfl_xor_sync(0xffffffffu, s1, 2);
        const float inv0 = __frcp_rn(s0);
        const float inv1 = __frcp_rn(s1);

        // ---- pack P directly into A fragments (no smem round-trip) ----
        uint32_t pa[4][4];
#pragma unroll
        for (int kt = 0; kt < 4; ++kt) {
            union { __half2 h; uint32_t u; } u0, u1, u2, u3;
            u0.h = __floats2half2_rn(sc[2 * kt][0] * inv0, sc[2 * kt][1] * inv0);
            u1.h = __floats2half2_rn(sc[2 * kt][2] * inv1, sc[2 * kt][3] * inv1);
            u2.h = __floats2half2_rn(sc[2 * kt + 1][0] * inv0, sc[2 * kt + 1][1] * inv0);
            u3.h = __floats2half2_rn(sc[2 * kt + 1][2] * inv1, sc[2 * kt + 1][3] * inv1);
            pa[kt][0] = u0.u; pa[kt][1] = u1.u; pa[kt][2] = u2.u; pa[kt][3] = u3.u;
        }

        // ---- O = P V : 16x32 per warp ----
        float oc[4][4];
#pragma unroll
        for (int nt = 0; nt < 4; ++nt)
#pragma unroll
            for (int c = 0; c < 4; ++c) oc[nt][c] = 0.f;

#pragma unroll
        for (int nt = 0; nt < 4; ++nt) {
#pragma unroll
            for (int hh = 0; hh < 2; ++hh) {
                uint32_t b0, b1, b2, b3;
                ldsm_x4_t(b0, b1, b2, b3,
                          sh_addr(&sV[(hh * 32 + bv_tok) * PADH + nt * 8]));
                mma_f16(oc[nt], pa[2 * hh], b0, b1);
                mma_f16(oc[nt], pa[2 * hh + 1], b2, b3);
            }
        }

        // ---- write O (same layout as input) ----
#pragma unroll
        for (int nt = 0; nt < 4; ++nt) {
            const int col = head * HEAD_DIM + nt * 8 + 2 * t;
            *(float2*)&out[obase0 + col] = make_float2(oc[nt][0], oc[nt][1]);
            *(float2*)&out[obase1 + col] = make_float2(oc[nt][2], oc[nt][3]);
        }
        __syncthreads();   // protect smem before next iteration's stage
    }
}

// ---------------------------------------------------------------------------
extern "C" void kernel_launch(void* const* d_in, const int* in_sizes, int n_in,
                              void* d_out, int out_size)
{
    const float* q = (const float*)d_in[0];
    const float* k = (const float*)d_in[1];
    const float* v = (const float*)d_in[2];
    // d_in[3] = H, d_in[4] = W (int32, fixed 256)
    const float* w_proj = (const float*)d_in[5];
    const float* b_proj = (const float*)d_in[6];
    const float* ln1_g  = (const float*)d_in[7];
    const float* ln1_b  = (const float*)d_in[8];
    const float* w1     = (const float*)d_in[9];
    const float* b1     = (const float*)d_in[10];
    const float* ln2_g  = (const float*)d_in[11];
    const float* ln2_b  = (const float*)d_in[12];
    const float* w2     = (const float*)d_in[13];
    const float* b2     = (const float*)d_in[14];
    const float* ln3_g  = (const float*)d_in[15];
    const float* ln3_b  = (const float*)d_in[16];
    const float* w3     = (const float*)d_in[17];
    const float* b3     = (const float*)d_in[18];

    int B = in_sizes[0] / (256 * 256 * DIM);

    cudaFuncSetAttribute(attn_kernel, cudaFuncAttributeMaxDynamicSharedMemorySize, SMEM_BYTES);

    rpe_mlp_kernel<<<1, 256>>>(w_proj, b_proj, ln1_g, ln1_b, w1, b1,
                               ln2_g, ln2_b, w2, b2, ln3_g, ln3_b, w3, b3);
    rpe_expand_kernel<<<NH * 64 * 64 / 256, 256>>>();
    attn_kernel<<<B * 1024, 256, SMEM_BYTES>>>(q, k, v, (float*)d_out);
}

// round 8
// speedup vs baseline: 6.4804x; 1.2231x over previous
#include <cuda_runtime.h>
#include <cuda_fp16.h>
#include <cstdint>

// Problem constants (fixed by reference setup)
#define HSZ 8
#define WSZ 8
#define NTOK 64
#define DIM 192
#define NH 6
#define HEAD_DIM 32
#define POS_DIM 12
#define NPOS 225
#define SCALE 0.17677669529663689f   // 32^-0.5

#define PADH 40      // halves per row, Q/K/V tiles (80B rows -> LDSM conflict-free)

// smem (in halves): two head slots, each {Q,K,V: 64*PADH}
#define SLOT_H   (3 * 64 * PADH)
#define SMH_Q(s) ((s) * SLOT_H)
#define SMH_K(s) (SMH_Q(s) + 64 * PADH)
#define SMH_V(s) (SMH_K(s) + 64 * PADH)
#define SMH_TOT  (2 * SLOT_H)
#define SMEM_BYTES (SMH_TOT * 2)

__device__ float g_pos[NPOS * NH];   // RPE MLP output (fp32, L1/L2-resident in attn)

// ---------------------------------------------------------------------------
// Kernel A (fused): weights -> smem, tiny MLP -> g_pos[225][6]
// ---------------------------------------------------------------------------
__device__ __forceinline__ void ln_relu_s(float* x, const float* g, const float* b, float* y) {
    float m = 0.f;
#pragma unroll
    for (int j = 0; j < POS_DIM; ++j) m += x[j];
    m *= (1.0f / POS_DIM);
    float v = 0.f;
#pragma unroll
    for (int j = 0; j < POS_DIM; ++j) { float d = x[j] - m; v += d * d; }
    v *= (1.0f / POS_DIM);
    float inv = rsqrtf(v + 1e-5f);
#pragma unroll
    for (int j = 0; j < POS_DIM; ++j) {
        float t = (x[j] - m) * inv * g[j] + b[j];
        y[j] = t > 0.f ? t : 0.f;
    }
}

__global__ void rpe_mlp_kernel(
    const float* __restrict__ w_proj, const float* __restrict__ b_proj,
    const float* __restrict__ ln1_g, const float* __restrict__ ln1_b,
    const float* __restrict__ w1, const float* __restrict__ b1,
    const float* __restrict__ ln2_g, const float* __restrict__ ln2_b,
    const float* __restrict__ w2, const float* __restrict__ b2,
    const float* __restrict__ ln3_g, const float* __restrict__ ln3_b,
    const float* __restrict__ w3, const float* __restrict__ b3)
{
    __shared__ float s_wp[2 * POS_DIM], s_bp[POS_DIM];
    __shared__ float s_g1[POS_DIM], s_c1[POS_DIM], s_w1[POS_DIM * POS_DIM], s_b1[POS_DIM];
    __shared__ float s_g2[POS_DIM], s_c2[POS_DIM], s_w2[POS_DIM * POS_DIM], s_b2[POS_DIM];
    __shared__ float s_g3[POS_DIM], s_c3[POS_DIM], s_w3[POS_DIM * NH], s_b3[NH];

    const int tid = threadIdx.x;
    for (int i = tid; i < POS_DIM * POS_DIM; i += 256) { s_w1[i] = w1[i]; s_w2[i] = w2[i]; }
    if (tid < POS_DIM * NH) s_w3[tid] = w3[tid];
    if (tid < 2 * POS_DIM) s_wp[tid] = w_proj[tid];
    if (tid < POS_DIM) {
        s_bp[tid] = b_proj[tid];
        s_g1[tid] = ln1_g[tid]; s_c1[tid] = ln1_b[tid]; s_b1[tid] = b1[tid];
        s_g2[tid] = ln2_g[tid]; s_c2[tid] = ln2_b[tid]; s_b2[tid] = b2[tid];
        s_g3[tid] = ln3_g[tid]; s_c3[tid] = ln3_b[tid];
    }
    if (tid < NH) s_b3[tid] = b3[tid];
    __syncthreads();

    const int m = tid;
    if (m >= NPOS) return;
    float in0 = (float)(m / (2 * WSZ - 1) - (HSZ - 1));
    float in1 = (float)(m % (2 * WSZ - 1) - (WSZ - 1));

    float x[POS_DIM], y[POS_DIM];
#pragma unroll
    for (int j = 0; j < POS_DIM; ++j)
        x[j] = in0 * s_wp[j] + in1 * s_wp[POS_DIM + j] + s_bp[j];

    ln_relu_s(x, s_g1, s_c1, y);
#pragma unroll
    for (int j = 0; j < POS_DIM; ++j) {
        float s = s_b1[j];
#pragma unroll
        for (int kk = 0; kk < POS_DIM; ++kk) s += y[kk] * s_w1[kk * POS_DIM + j];
        x[j] = s;
    }
    ln_relu_s(x, s_g2, s_c2, y);
#pragma unroll
    for (int j = 0; j < POS_DIM; ++j) {
        float s = s_b2[j];
#pragma unroll
        for (int kk = 0; kk < POS_DIM; ++kk) s += y[kk] * s_w2[kk * POS_DIM + j];
        x[j] = s;
    }
    ln_relu_s(x, s_g3, s_c3, y);
#pragma unroll
    for (int h = 0; h < NH; ++h) {
        float s = s_b3[h];
#pragma unroll
        for (int kk = 0; kk < POS_DIM; ++kk) s += y[kk] * s_w3[kk * NH + h];
        g_pos[m * NH + h] = s;
    }
}

// ---------------------------------------------------------------------------
// MMA / LDSM helpers
// ---------------------------------------------------------------------------
__device__ __forceinline__ uint32_t sh_addr(const void* p) {
    return (uint32_t)__cvta_generic_to_shared(p);
}
__device__ __forceinline__ void ldsm_x4(uint32_t& r0, uint32_t& r1, uint32_t& r2, uint32_t& r3, uint32_t a) {
    asm volatile("ldmatrix.sync.aligned.m8n8.x4.shared.b16 {%0,%1,%2,%3},[%4];"
                 : "=r"(r0), "=r"(r1), "=r"(r2), "=r"(r3) : "r"(a));
}
__device__ __forceinline__ void ldsm_x4_t(uint32_t& r0, uint32_t& r1, uint32_t& r2, uint32_t& r3, uint32_t a) {
    asm volatile("ldmatrix.sync.aligned.m8n8.x4.trans.shared.b16 {%0,%1,%2,%3},[%4];"
                 : "=r"(r0), "=r"(r1), "=r"(r2), "=r"(r3) : "r"(a));
}
__device__ __forceinline__ void mma_f16(float c[4], const uint32_t a[4], uint32_t b0, uint32_t b1) {
    asm volatile("mma.sync.aligned.m16n8k16.row.col.f32.f16.f16.f32 "
                 "{%0,%1,%2,%3},{%4,%5,%6,%7},{%8,%9},{%0,%1,%2,%3};"
                 : "+f"(c[0]), "+f"(c[1]), "+f"(c[2]), "+f"(c[3])
                 : "r"(a[0]), "r"(a[1]), "r"(a[2]), "r"(a[3]), "r"(b0), "r"(b1));
}
__device__ __forceinline__ void st_half8(__half* p, float4 f0, float4 f1) {
    union { __half2 h[4]; uint4 u; } t;
    t.h[0] = __floats2half2_rn(f0.x, f0.y);
    t.h[1] = __floats2half2_rn(f0.z, f0.w);
    t.h[2] = __floats2half2_rn(f1.x, f1.y);
    t.h[3] = __floats2half2_rn(f1.z, f1.w);
    *(uint4*)p = t.u;
}

// ---------------------------------------------------------------------------
// Kernel B: one CTA per 8x8 window. 3 iterations of 2 heads.
// 8 warps = 4 m-tiles x 2 heads; warp computes full 16x64 score rows.
// Bias read directly from g_pos (L1-resident) at softmax time.
// ---------------------------------------------------------------------------
__global__ __launch_bounds__(256, 4) void attn_kernel(
    const float* __restrict__ q, const float* __restrict__ k,
    const float* __restrict__ v, float* __restrict__ out)
{
    extern __shared__ __half smh[];

    const int tid = threadIdx.x;
    const int lane = tid & 31;
    const int wid = tid >> 5;
    const int g = lane >> 2;       // 0..7
    const int t = lane & 3;        // 0..3
    const int m = wid & 3;         // m-tile
    const int hs = wid >> 2;       // head slot (0/1)

    const int w = blockIdx.x;
    const int b = w >> 10;
    const int wy = (w >> 5) & 31;
    const int wx = w & 31;

    // staging addresses: thread handles token tid>>2, channels (tid&3)*8..+8
    const int stok = tid >> 2;
    const int sch = (tid & 3) * 8;
    const int sy = wy * HSZ + (stok >> 3);
    const int sx = wx * WSZ + (stok & 7);
    const int gtok = ((b * 256 + sy) * 256 + sx) * DIM + sch;
    const int soff = stok * PADH + sch;

    // this warp's output rows
    const int r0 = m * 16 + g;
    const int r1 = r0 + 8;
    const int y0 = r0 >> 3, x0 = r0 & 7;   // r1: y0+1, x0
    const int obase0 = ((b * 256 + wy * HSZ + y0) * 256 + wx * WSZ + x0) * DIM;
    const int obase1 = obase0 + 256 * DIM; // r1 is one image row below r0

    // bias base: index for (row r0, col nt*8 + 2t) = ((y0 - nt + 7)*15 + (x0 - 2t + 7))*6 + head
    const int bias0 = ((y0 + 7) * 15 + (x0 - 2 * t + 7)) * NH;   // subtract nt*90 per step

    // LDSM lane addressing
    const int a_row = m * 16 + (lane & 7) + ((lane >> 3) & 1) * 8;
    const int a_colp = (lane >> 4) * 8;
    const int bk_row = lane & 7;
    const int bk_col = (lane >> 3) * 8;
    const int bv_tok = (lane >> 3) * 8 + (lane & 7);

#pragma unroll 1
    for (int it = 0; it < 3; ++it) {
        const int h0 = it * 2;

        // ---- stage 2 heads: Q(scaled),K,V as fp16 ----
#pragma unroll
        for (int s = 0; s < 2; ++s) {
            const int go = gtok + (h0 + s) * HEAD_DIM;
            float4 f0, f1;
            f0 = *(const float4*)(q + go);
            f1 = *(const float4*)(q + go + 4);
            f0.x *= SCALE; f0.y *= SCALE; f0.z *= SCALE; f0.w *= SCALE;
            f1.x *= SCALE; f1.y *= SCALE; f1.z *= SCALE; f1.w *= SCALE;
            st_half8(&smh[SMH_Q(s) + soff], f0, f1);
            f0 = *(const float4*)(k + go);
            f1 = *(const float4*)(k + go + 4);
            st_half8(&smh[SMH_K(s) + soff], f0, f1);
            f0 = *(const float4*)(v + go);
            f1 = *(const float4*)(v + go + 4);
            st_half8(&smh[SMH_V(s) + soff], f0, f1);
        }
        __syncthreads();

        const __half* sQ = &smh[SMH_Q(hs)];
        const __half* sK = &smh[SMH_K(hs)];
        const __half* sV = &smh[SMH_V(hs)];
        const int head = h0 + hs;
        const float* gp = g_pos + head;

        // ---- S = Q K^T : 16x64 per warp ----
        float sc[8][4];
#pragma unroll
        for (int nt = 0; nt < 8; ++nt)
#pragma unroll
            for (int c = 0; c < 4; ++c) sc[nt][c] = 0.f;

        uint32_t aq[2][4];
#pragma unroll
        for (int kt = 0; kt < 2; ++kt)
            ldsm_x4(aq[kt][0], aq[kt][1], aq[kt][2], aq[kt][3],
                    sh_addr(&sQ[a_row * PADH + kt * 16 + a_colp]));

#pragma unroll
        for (int nt = 0; nt < 8; ++nt) {
            uint32_t b0, b1, b2, b3;
            ldsm_x4(b0, b1, b2, b3, sh_addr(&sK[(nt * 8 + bk_row) * PADH + bk_col]));
            mma_f16(sc[nt], aq[0], b0, b1);
            mma_f16(sc[nt], aq[1], b2, b3);
        }

        // ---- bias add (direct from g_pos, L1 hits) + warp-local softmax ----
        float mx0 = -1e30f, mx1 = -1e30f;
#pragma unroll
        for (int nt = 0; nt < 8; ++nt) {
            // base index for (r0, col nt*8+2t): bias drops by 90 per nt step
            const float* p = gp + bias0 - nt * 15 * NH;
            // col+1 => dx-1 => -NH ; row r1 => dy+1 => +15*NH
            sc[nt][0] += p[0];
            sc[nt][1] += p[-NH];
            sc[nt][2] += p[15 * NH];
            sc[nt][3] += p[15 * NH - NH];
            mx0 = fmaxf(mx0, fmaxf(sc[nt][0], sc[nt][1]));
            mx1 = fmaxf(mx1, fmaxf(sc[nt][2], sc[nt][3]));
        }
        mx0 = fmaxf(mx0, __shfl_xor_sync(0xffffffffu, mx0, 1));
        mx0 = fmaxf(mx0, __shfl_xor_sync(0xffffffffu, mx0, 2));
        mx1 = fmaxf(mx1, __shfl_xor_sync(0xffffffffu, mx1, 1));
        mx1 = fmaxf(mx1, __shfl_xor_sync(0xffffffffu, mx1, 2));

        float s0 = 0.f, s1 = 0.f;
#pragma unroll
        for (int nt = 0; nt < 8; ++nt) {
            sc[nt][0] = __expf(sc[nt][0] - mx0);
            sc[nt][1] = __expf(sc[nt][1] - mx0);
            sc[nt][2] = __expf(sc[nt][2] - mx1);
            sc[nt][3] = __expf(sc[nt][3] - mx1);
            s0 += sc[nt][0] + sc[nt][1];
            s1 += sc[nt][2] + sc[nt][3];
        }
        s0 += __shfl_xor_sync(0xffffffffu, s0, 1);
        s0 += __shfl_xor_sync(0xffffffffu, s0, 2);
        s1 += __shfl_xor_sync(0xffffffffu, s1, 1);
        s1 += __shfl_xor_sync(0xffffffffu, s1, 2);
        const float inv0 = __frcp_rn(s0);
        const float inv1 = __frcp_rn(s1);

        // ---- pack P directly into A fragments (no smem round-trip) ----
        uint32_t pa[4][4];
#pragma unroll
        for (int kt = 0; kt < 4; ++kt) {
            union { __half2 h; uint32_t u; } u0, u1, u2, u3;
            u0.h = __floats2half2_rn(sc[2 * kt][0] * inv0, sc[2 * kt][1] * inv0);
            u1.h = __floats2half2_rn(sc[2 * kt][2] * inv1, sc[2 * kt][3] * inv1);
            u2.h = __floats2half2_rn(sc[2 * kt + 1][0] * inv0, sc[2 * kt + 1][1] * inv0);
            u3.h = __floats2half2_rn(sc[2 * kt + 1][2] * inv1, sc[2 * kt + 1][3] * inv1);
            pa[kt][0] = u0.u; pa[kt][1] = u1.u; pa[kt][2] = u2.u; pa[kt][3] = u3.u;
        }

        // ---- O = P V : 16x32 per warp; per-nt accumulators (low reg pressure) ----
        const int ocol = head * HEAD_DIM + 2 * t;
#pragma unroll
        for (int nt = 0; nt < 4; ++nt) {
            float oc[4] = {0.f, 0.f, 0.f, 0.f};
#pragma unroll
            for (int hh = 0; hh < 2; ++hh) {
                uint32_t b0, b1, b2, b3;
                ldsm_x4_t(b0, b1, b2, b3,
                          sh_addr(&sV[(hh * 32 + bv_tok) * PADH + nt * 8]));
                mma_f16(oc, pa[2 * hh], b0, b1);
                mma_f16(oc, pa[2 * hh + 1], b2, b3);
            }
            *(float2*)&out[obase0 + ocol + nt * 8] = make_float2(oc[0], oc[1]);
            *(float2*)&out[obase1 + ocol + nt * 8] = make_float2(oc[2], oc[3]);
        }
        __syncthreads();   // protect smem before next iteration's stage
    }
}

// ---------------------------------------------------------------------------
extern "C" void kernel_launch(void* const* d_in, const int* in_sizes, int n_in,
                              void* d_out, int out_size)
{
    const float* q = (const float*)d_in[0];
    const float* k = (const float*)d_in[1];
    const float* v = (const float*)d_in[2];
    // d_in[3] = H, d_in[4] = W (int32, fixed 256)
    const float* w_proj = (const float*)d_in[5];
    const float* b_proj = (const float*)d_in[6];
    const float* ln1_g  = (const float*)d_in[7];
    const float* ln1_b  = (const float*)d_in[8];
    const float* w1     = (const float*)d_in[9];
    const float* b1     = (const float*)d_in[10];
    const float* ln2_g  = (const float*)d_in[11];
    const float* ln2_b  = (const float*)d_in[12];
    const float* w2     = (const float*)d_in[13];
    const float* b2     = (const float*)d_in[14];
    const float* ln3_g  = (const float*)d_in[15];
    const float* ln3_b  = (const float*)d_in[16];
    const float* w3     = (const float*)d_in[17];
    const float* b3     = (const float*)d_in[18];

    int B = in_sizes[0] / (256 * 256 * DIM);

    cudaFuncSetAttribute(attn_kernel, cudaFuncAttributeMaxDynamicSharedMemorySize, SMEM_BYTES);

    rpe_mlp_kernel<<<1, 256>>>(w_proj, b_proj, ln1_g, ln1_b, w1, b1,
                               ln2_g, ln2_b, w2, b2, ln3_g, ln3_b, w3, b3);
    attn_kernel<<<B * 1024, 256, SMEM_BYTES>>>(q, k, v, (float*)d_out);
}